// round 11
// baseline (speedup 1.0000x reference)
#include <cuda_runtime.h>
#include <cuda_bf16.h>
#include <math_constants.h>

// Problem shape (fixed by the reference): B=2, H=16, N=2048, D=64.
#define BB      2
#define HH      16
#define NSEQ    2048
#define DD      64
#define TQ      16      // q rows per CTA
#define NTHR    256
#define CHUNK   256     // compacted key columns per SMEM chunk

// Dynamic SMEM layout (bytes):
//   S      : TQ*NSEQ floats   = 131072
//   buf    : 64*CHUNK floats  =  65536   (kbuf_t[d][jj] for GEMM1, vbuf[jj][d] for GEMM2)
//   qs     : TQ*DD floats     =   4096
//   idx    : NSEQ u16         =   4096
//   pos    : NSEQ u16         =   4096
//   flags  : NSEQ u8          =   2048
//   inv_s  : TQ floats        =     64
//   qrow   : TQ ints          =     64
//   rowpos : TQ ints          =     64
//   meta   : 2 ints           =      8
#define SMEM_BYTES (131072 + 65536 + 4096 + 4096 + 4096 + 2048 + 64 + 64 + 64 + 8)

__device__ float g_vmean[BB * HH * DD];

// Per-(b,h) column mean of V: output for fully-masked q rows is exactly this.
__global__ void vmean_kernel(const float* __restrict__ v)
{
    int bh = blockIdx.x;
    int d = threadIdx.x & 63;
    int part = threadIdx.x >> 6;
    const float* vp = v + (size_t)bh * NSEQ * DD;
    float s = 0.f;
    int j0 = part * (NSEQ / 4);
    for (int j = j0; j < j0 + NSEQ / 4; j++)
        s += vp[(size_t)j * DD + d];
    __shared__ float red[256];
    red[threadIdx.x] = s;
    __syncthreads();
    if (part == 0) {
        float t = red[d] + red[64 + d] + red[128 + d] + red[192 + d];
        g_vmean[bh * DD + d] = t * (1.0f / 2048.0f);
    }
}

__device__ __forceinline__ float f4c(const float4& f, int i)
{
    return (i == 0) ? f.x : (i == 1) ? f.y : (i == 2) ? f.z : f.w;
}

__global__ __launch_bounds__(NTHR, 1)
void attn_kernel(const float* __restrict__ q,
                 const float* __restrict__ k,
                 const float* __restrict__ v,
                 const int* __restrict__ mask,
                 float* __restrict__ out)
{
    extern __shared__ float smem[];
    float* S   = smem;                      // [TQ][NSEQ] (compacted rows x compacted cols used)
    float* buf = S + TQ * NSEQ;             // 64*CHUNK
    float* qs  = buf + 64 * CHUNK;          // [TQ][DD], compacted rows, pre-scaled by 1/8
    unsigned short* idx   = (unsigned short*)(qs + TQ * DD); // unmasked col indices (ascending)
    unsigned short* pos   = idx + NSEQ;                      // col j -> compacted rank
    unsigned char*  flags = (unsigned char*)(pos + NSEQ);    // 1 = masked
    float* inv_s = (float*)(flags + NSEQ);  // 1/rowsum per compacted row
    int* qrow   = (int*)(inv_s + TQ);       // compacted row -> tile row index
    int* rowpos = qrow + TQ;                // tile row -> compacted row (-1 = masked)
    int* meta   = rowpos + TQ;              // [0]=m (unmasked cols), [1]=nr (unmasked rows)

    const int tid  = threadIdx.x;
    const int bh   = blockIdx.y;
    const int b    = bh >> 4;               // H = 16
    const int q0   = blockIdx.x * TQ;
    const int lane = tid & 31;

    // ---- column compaction over the batch mask (warp 0, deterministic order) ----
    if (tid < 32) {
        int total = 0;
        const int* mp = mask + (size_t)b * NSEQ;
        for (int base = 0; base < NSEQ; base += 32) {
            int mv = mp[base + lane];
            bool un = (mv == 0);
            flags[base + lane] = un ? 0 : 1;
            unsigned bal = __ballot_sync(0xffffffffu, un);
            int pre = __popc(bal & ((1u << lane) - 1u));
            if (un) idx[total + pre] = (unsigned short)(base + lane);
            pos[base + lane] = (unsigned short)(total + pre);
            total += __popc(bal);
        }
        if (lane == 0) meta[0] = total;
    }
    __syncthreads();
    if (tid == 0) {
        int nr = 0;
        for (int i = 0; i < TQ; i++) {
            if (!flags[q0 + i]) { qrow[nr] = i; rowpos[i] = nr; nr++; }
            else rowpos[i] = -1;
        }
        meta[1] = nr;
    }
    for (int t = tid; t < TQ * DD; t += NTHR) qs[t] = 0.f;
    __syncthreads();
    const int m  = meta[0];
    const int nr = meta[1];

    // ---- load compacted Q rows, scaled by 1/TEMPERATURE = 0.125 ----
    {
        const float4* qg = (const float4*)q;
        for (int t = tid; t < nr * (DD / 4); t += NTHR) {
            int sr = t >> 4, d4 = t & 15;
            float4 qq = qg[((size_t)bh * NSEQ + q0 + qrow[sr]) * (DD / 4) + d4];
            qq.x *= 0.125f; qq.y *= 0.125f; qq.z *= 0.125f; qq.w *= 0.125f;
            *(float4*)&qs[sr * DD + d4 * 4] = qq;
        }
    }
    __syncthreads();

    const int ct = tid & 63;   // column tile (4 cols)
    const int rt = tid >> 6;   // row tile (4 rows)

    const int d_o  = tid & 63; // GEMM2 mapping
    const int srb  = tid >> 6;
    float oacc[4] = {0.f, 0.f, 0.f, 0.f};

    if (m > 0) {
        // ===== GEMM1: S[sr][jj] = (q/8)[sr,:] . K[idx[jj],:]  (compacted) =====
        const float4* kg = (const float4*)(k + (size_t)bh * NSEQ * DD);
        for (int cb = 0; cb < m; cb += CHUNK) {
            int cols = min(CHUNK, m - cb);
            int total4 = cols * (DD / 4);
            // gather K rows -> transposed SMEM buf[d][jj] (conflict-free STS & LDS)
            for (int t = tid; t < total4; t += NTHR) {
                int d4, jj;
                if (cols == CHUNK) { d4 = t >> 8; jj = t & 255; }
                else { d4 = t / cols; jj = t - d4 * cols; }
                int row = idx[cb + jj];
                float4 kk = kg[(size_t)row * (DD / 4) + d4];
                buf[(d4 * 4 + 0) * CHUNK + jj] = kk.x;
                buf[(d4 * 4 + 1) * CHUNK + jj] = kk.y;
                buf[(d4 * 4 + 2) * CHUNK + jj] = kk.z;
                buf[(d4 * 4 + 3) * CHUNK + jj] = kk.w;
            }
            __syncthreads();
            if (rt * 4 < nr) {
                float acc[4][4];
                #pragma unroll
                for (int r = 0; r < 4; r++)
                    #pragma unroll
                    for (int c = 0; c < 4; c++) acc[r][c] = 0.f;
                #pragma unroll
                for (int d4 = 0; d4 < 16; d4++) {
                    float4 qv[4];
                    #pragma unroll
                    for (int r = 0; r < 4; r++)
                        qv[r] = *(const float4*)&qs[(rt * 4 + r) * DD + d4 * 4];
                    #pragma unroll
                    for (int t4 = 0; t4 < 4; t4++) {
                        float4 kv = *(const float4*)&buf[(d4 * 4 + t4) * CHUNK + ct * 4];
                        #pragma unroll
                        for (int r = 0; r < 4; r++) {
                            float qd = f4c(qv[r], t4);
                            acc[r][0] += qd * kv.x;
                            acc[r][1] += qd * kv.y;
                            acc[r][2] += qd * kv.z;
                            acc[r][3] += qd * kv.w;
                        }
                    }
                }
                int colrem = cols - ct * 4;
                #pragma unroll
                for (int r = 0; r < 4; r++) {
                    int sr = rt * 4 + r;
                    if (sr < nr && colrem > 0) {
                        float* sp = &S[sr * NSEQ + cb + ct * 4];
                        if (colrem >= 4) {
                            *(float4*)sp = make_float4(acc[r][0], acc[r][1], acc[r][2], acc[r][3]);
                        } else {
                            for (int c = 0; c < colrem; c++) sp[c] = acc[r][c];
                        }
                    }
                }
            }
            __syncthreads();
        }

        // ===== softmax (max, exp in place) over compacted columns =====
        {
            int row = tid >> 4;     // compacted row handled by a 16-lane group
            int g   = tid & 15;
            float rmax = -CUDART_INF_F;
            if (row < nr)
                for (int jj = g; jj < m; jj += 16)
                    rmax = fmaxf(rmax, S[row * NSEQ + jj]);
            #pragma unroll
            for (int s = 8; s; s >>= 1)
                rmax = fmaxf(rmax, __shfl_xor_sync(0xffffffffu, rmax, s, 16));
            float lsum = 0.f;
            if (row < nr)
                for (int jj = g; jj < m; jj += 16) {
                    float e = __expf(S[row * NSEQ + jj] - rmax);
                    S[row * NSEQ + jj] = e;
                    lsum += e;
                }
            #pragma unroll
            for (int s = 8; s; s >>= 1)
                lsum += __shfl_xor_sync(0xffffffffu, lsum, s, 16);
            if (g == 0 && row < nr) inv_s[row] = 1.0f / lsum;
        }
        __syncthreads();

        // ===== GEMM2: O[sr][d] = (sum_jj E[sr][jj] * V[idx[jj]][d]) * inv =====
        const float4* vg = (const float4*)(v + (size_t)bh * NSEQ * DD);
        for (int cb = 0; cb < m; cb += CHUNK) {
            int cols = min(CHUNK, m - cb);
            int total4 = cols * (DD / 4);
            for (int t = tid; t < total4; t += NTHR) {
                int jj = t >> 4, d4 = t & 15;
                int row = idx[cb + jj];
                float4 vv = vg[(size_t)row * (DD / 4) + d4];
                *(float4*)&buf[jj * DD + d4 * 4] = vv;
            }
            __syncthreads();
            if (srb * 4 < nr) {
                int jj = 0;
                for (; jj + 4 <= cols; jj += 4) {
                    float4 sv[4];
                    #pragma unroll
                    for (int r = 0; r < 4; r++)
                        sv[r] = *(const float4*)&S[(srb * 4 + r) * NSEQ + cb + jj];
                    #pragma unroll
                    for (int t4 = 0; t4 < 4; t4++) {
                        float vv = buf[(jj + t4) * DD + d_o];
                        #pragma unroll
                        for (int r = 0; r < 4; r++)
                            oacc[r] += f4c(sv[r], t4) * vv;
                    }
                }
                for (; jj < cols; jj++) {
                    float vv = buf[jj * DD + d_o];
                    #pragma unroll
                    for (int r = 0; r < 4; r++)
                        oacc[r] += S[(srb * 4 + r) * NSEQ + cb + jj] * vv;
                }
            }
            __syncthreads();
        }
        // write O for unmasked rows
        if (srb * 4 < nr) {
            #pragma unroll
            for (int r = 0; r < 4; r++) {
                int sr = srb * 4 + r;
                if (sr < nr)
                    out[((size_t)bh * NSEQ + q0 + qrow[sr]) * DD + d_o] = oacc[r] * inv_s[sr];
            }
        }
    } // m > 0

    // ===== attn write: full rows; masked rows (or m==0) are exactly uniform 1/2048 =====
    {
        float* attn = out + (size_t)BB * HH * NSEQ * DD;
        for (int i = 0; i < TQ; i++) {
            float4* rowp = (float4*)(attn + ((size_t)bh * NSEQ + q0 + i) * NSEQ);
            int sr = rowpos[i];
            if (m == 0 || sr < 0) {
                const float u = 1.0f / 2048.0f;
                float4 val = make_float4(u, u, u, u);
                for (int j4 = tid; j4 < NSEQ / 4; j4 += NTHR) rowp[j4] = val;
            } else {
                float iv = inv_s[sr];
                const float* Sp = &S[sr * NSEQ];
                for (int j4 = tid; j4 < NSEQ / 4; j4 += NTHR) {
                    int j = j4 * 4;
                    float4 o;
                    o.x = flags[j + 0] ? 0.f : Sp[pos[j + 0]] * iv;
                    o.y = flags[j + 1] ? 0.f : Sp[pos[j + 1]] * iv;
                    o.z = flags[j + 2] ? 0.f : Sp[pos[j + 2]] * iv;
                    o.w = flags[j + 3] ? 0.f : Sp[pos[j + 3]] * iv;
                    rowp[j4] = o;
                }
            }
        }
    }

    // ===== masked-row outputs (and all rows when m==0): colmean(V) =====
    for (int t = tid; t < TQ * DD; t += NTHR) {
        int i = t >> 6, dd2 = t & 63;
        if (m == 0 || rowpos[i] < 0)
            out[((size_t)bh * NSEQ + q0 + i) * DD + dd2] = g_vmean[bh * DD + dd2];
    }
}

extern "C" void kernel_launch(void* const* d_in, const int* in_sizes, int n_in,
                              void* d_out, int out_size)
{
    const float* q    = (const float*)d_in[0];
    const float* k    = (const float*)d_in[1];
    const float* v    = (const float*)d_in[2];
    const int*   mask = (const int*)d_in[3];
    float* out = (float*)d_out;

    // Opt-in to >48KB dynamic SMEM (idempotent; not a stream op, capture-safe).
    cudaFuncSetAttribute(attn_kernel, cudaFuncAttributeMaxDynamicSharedMemorySize, SMEM_BYTES);

    vmean_kernel<<<BB * HH, 256>>>(v);

    dim3 grid(NSEQ / TQ, BB * HH);
    attn_kernel<<<grid, NTHR, SMEM_BYTES>>>(q, k, v, mask, out);
}

// round 13
// speedup vs baseline: 1.0062x; 1.0062x over previous
#include <cuda_runtime.h>
#include <cuda_bf16.h>
#include <math_constants.h>

// Problem shape (fixed by the reference): B=2, H=16, N=2048, D=64.
#define BB      2
#define HH      16
#define NSEQ    2048
#define DD      64
#define TQ      16      // q rows per CTA
#define NTHR    256
#define CHUNK   256     // compacted key columns per SMEM chunk

// Dynamic SMEM layout (bytes):
//   S      : TQ*NSEQ floats   = 131072
//   buf    : 64*CHUNK floats  =  65536   (kbuf_t[d][jj] for GEMM1, vbuf[jj][d] for GEMM2)
//   qs     : TQ*DD floats     =   4096
//   idx    : NSEQ u16         =   4096
//   pos    : NSEQ u16         =   4096
//   flags  : NSEQ u8          =   2048
//   inv_s  : TQ floats        =     64
//   qrow   : TQ ints          =     64
//   rowpos : TQ ints          =     64
//   meta   : 2 ints           =      8
#define SMEM_BYTES (131072 + 65536 + 4096 + 4096 + 4096 + 2048 + 64 + 64 + 64 + 8)

__device__ float g_vmean[BB * HH * DD];

// Per-(b,h) column mean of V: output for fully-masked q rows is exactly this.
__global__ void vmean_kernel(const float* __restrict__ v)
{
    int bh = blockIdx.x;
    int d = threadIdx.x & 63;
    int part = threadIdx.x >> 6;
    const float* vp = v + (size_t)bh * NSEQ * DD;
    float s = 0.f;
    int j0 = part * (NSEQ / 4);
    for (int j = j0; j < j0 + NSEQ / 4; j++)
        s += vp[(size_t)j * DD + d];
    __shared__ float red[256];
    red[threadIdx.x] = s;
    __syncthreads();
    if (part == 0) {
        float t = red[d] + red[64 + d] + red[128 + d] + red[192 + d];
        g_vmean[bh * DD + d] = t * (1.0f / 2048.0f);
    }
}

__device__ __forceinline__ float f4c(const float4& f, int i)
{
    return (i == 0) ? f.x : (i == 1) ? f.y : (i == 2) ? f.z : f.w;
}

__global__ __launch_bounds__(NTHR, 1)
void attn_kernel(const float* __restrict__ q,
                 const float* __restrict__ k,
                 const float* __restrict__ v,
                 const int* __restrict__ mask,
                 float* __restrict__ out)
{
    extern __shared__ float smem[];
    float* S   = smem;                      // [TQ][NSEQ] (compacted rows x compacted cols used)
    float* buf = S + TQ * NSEQ;             // 64*CHUNK
    float* qs  = buf + 64 * CHUNK;          // [TQ][DD], compacted rows, pre-scaled by 1/8
    unsigned short* idx   = (unsigned short*)(qs + TQ * DD); // unmasked col indices (ascending)
    unsigned short* pos   = idx + NSEQ;                      // col j -> compacted rank
    unsigned char*  flags = (unsigned char*)(pos + NSEQ);    // 1 = masked
    float* inv_s = (float*)(flags + NSEQ);  // 1/rowsum per compacted row
    int* qrow   = (int*)(inv_s + TQ);       // compacted row -> tile row index
    int* rowpos = qrow + TQ;                // tile row -> compacted row (-1 = masked)
    int* meta   = rowpos + TQ;              // [0]=m (unmasked cols), [1]=nr (unmasked rows)

    const int tid  = threadIdx.x;
    const int bh   = blockIdx.y;
    const int b    = bh >> 4;               // H = 16
    const int q0   = blockIdx.x * TQ;
    const int lane = tid & 31;

    // ---- column compaction over the batch mask (warp 0, deterministic order) ----
    if (tid < 32) {
        int total = 0;
        const int* mp = mask + (size_t)b * NSEQ;
        for (int base = 0; base < NSEQ; base += 32) {
            int mv = mp[base + lane];
            bool un = (mv == 0);
            flags[base + lane] = un ? 0 : 1;
            unsigned bal = __ballot_sync(0xffffffffu, un);
            int pre = __popc(bal & ((1u << lane) - 1u));
            if (un) idx[total + pre] = (unsigned short)(base + lane);
            pos[base + lane] = (unsigned short)(total + pre);
            total += __popc(bal);
        }
        if (lane == 0) meta[0] = total;
    }
    __syncthreads();
    if (tid == 0) {
        int nr = 0;
        for (int i = 0; i < TQ; i++) {
            if (!flags[q0 + i]) { qrow[nr] = i; rowpos[i] = nr; nr++; }
            else rowpos[i] = -1;
        }
        meta[1] = nr;
    }
    for (int t = tid; t < TQ * DD; t += NTHR) qs[t] = 0.f;
    __syncthreads();
    const int m  = meta[0];
    const int nr = meta[1];

    // ---- load compacted Q rows, scaled by 1/TEMPERATURE = 0.125 ----
    {
        const float4* qg = (const float4*)q;
        for (int t = tid; t < nr * (DD / 4); t += NTHR) {
            int sr = t >> 4, d4 = t & 15;
            float4 qq = qg[((size_t)bh * NSEQ + q0 + qrow[sr]) * (DD / 4) + d4];
            qq.x *= 0.125f; qq.y *= 0.125f; qq.z *= 0.125f; qq.w *= 0.125f;
            *(float4*)&qs[sr * DD + d4 * 4] = qq;
        }
    }
    __syncthreads();

    const int ct = tid & 63;   // column tile (4 cols)
    const int rt = tid >> 6;   // row tile (4 rows)

    const int d_o  = tid & 63; // GEMM2 mapping
    const int srb  = tid >> 6;
    float oacc[4] = {0.f, 0.f, 0.f, 0.f};

    if (m > 0) {
        // ===== GEMM1: S[sr][jj] = (q/8)[sr,:] . K[idx[jj],:]  (compacted) =====
        const float4* kg = (const float4*)(k + (size_t)bh * NSEQ * DD);
        for (int cb = 0; cb < m; cb += CHUNK) {
            int cols = min(CHUNK, m - cb);
            int total4 = cols * (DD / 4);
            // gather K rows -> transposed SMEM buf[d][jj] (conflict-free STS & LDS)
            for (int t = tid; t < total4; t += NTHR) {
                int d4, jj;
                if (cols == CHUNK) { d4 = t >> 8; jj = t & 255; }
                else { d4 = t / cols; jj = t - d4 * cols; }
                int row = idx[cb + jj];
                float4 kk = kg[(size_t)row * (DD / 4) + d4];
                buf[(d4 * 4 + 0) * CHUNK + jj] = kk.x;
                buf[(d4 * 4 + 1) * CHUNK + jj] = kk.y;
                buf[(d4 * 4 + 2) * CHUNK + jj] = kk.z;
                buf[(d4 * 4 + 3) * CHUNK + jj] = kk.w;
            }
            __syncthreads();
            if (rt * 4 < nr) {
                float acc[4][4];
                #pragma unroll
                for (int r = 0; r < 4; r++)
                    #pragma unroll
                    for (int c = 0; c < 4; c++) acc[r][c] = 0.f;
                #pragma unroll
                for (int d4 = 0; d4 < 16; d4++) {
                    float4 qv[4];
                    #pragma unroll
                    for (int r = 0; r < 4; r++)
                        qv[r] = *(const float4*)&qs[(rt * 4 + r) * DD + d4 * 4];
                    #pragma unroll
                    for (int t4 = 0; t4 < 4; t4++) {
                        float4 kv = *(const float4*)&buf[(d4 * 4 + t4) * CHUNK + ct * 4];
                        #pragma unroll
                        for (int r = 0; r < 4; r++) {
                            float qd = f4c(qv[r], t4);
                            acc[r][0] += qd * kv.x;
                            acc[r][1] += qd * kv.y;
                            acc[r][2] += qd * kv.z;
                            acc[r][3] += qd * kv.w;
                        }
                    }
                }
                int colrem = cols - ct * 4;
                #pragma unroll
                for (int r = 0; r < 4; r++) {
                    int sr = rt * 4 + r;
                    if (sr < nr && colrem > 0) {
                        float* sp = &S[sr * NSEQ + cb + ct * 4];
                        if (colrem >= 4) {
                            *(float4*)sp = make_float4(acc[r][0], acc[r][1], acc[r][2], acc[r][3]);
                        } else {
                            for (int c = 0; c < colrem; c++) sp[c] = acc[r][c];
                        }
                    }
                }
            }
            __syncthreads();
        }

        // ===== softmax (max, exp in place) over compacted columns =====
        {
            int row = tid >> 4;     // compacted row handled by a 16-lane group
            int g   = tid & 15;
            float rmax = -CUDART_INF_F;
            if (row < nr)
                for (int jj = g; jj < m; jj += 16)
                    rmax = fmaxf(rmax, S[row * NSEQ + jj]);
            #pragma unroll
            for (int s = 8; s; s >>= 1)
                rmax = fmaxf(rmax, __shfl_xor_sync(0xffffffffu, rmax, s, 16));
            float lsum = 0.f;
            if (row < nr)
                for (int jj = g; jj < m; jj += 16) {
                    float e = __expf(S[row * NSEQ + jj] - rmax);
                    S[row * NSEQ + jj] = e;
                    lsum += e;
                }
            #pragma unroll
            for (int s = 8; s; s >>= 1)
                lsum += __shfl_xor_sync(0xffffffffu, lsum, s, 16);
            if (g == 0 && row < nr) inv_s[row] = 1.0f / lsum;
        }
        __syncthreads();

        // ===== GEMM2: O[sr][d] = (sum_jj E[sr][jj] * V[idx[jj]][d]) * inv =====
        const float4* vg = (const float4*)(v + (size_t)bh * NSEQ * DD);
        for (int cb = 0; cb < m; cb += CHUNK) {
            int cols = min(CHUNK, m - cb);
            int total4 = cols * (DD / 4);
            for (int t = tid; t < total4; t += NTHR) {
                int jj = t >> 4, d4 = t & 15;
                int row = idx[cb + jj];
                float4 vv = vg[(size_t)row * (DD / 4) + d4];
                *(float4*)&buf[jj * DD + d4 * 4] = vv;
            }
            __syncthreads();
            if (srb * 4 < nr) {
                int jj = 0;
                for (; jj + 4 <= cols; jj += 4) {
                    float4 sv[4];
                    #pragma unroll
                    for (int r = 0; r < 4; r++)
                        sv[r] = *(const float4*)&S[(srb * 4 + r) * NSEQ + cb + jj];
                    #pragma unroll
                    for (int t4 = 0; t4 < 4; t4++) {
                        float vv = buf[(jj + t4) * DD + d_o];
                        #pragma unroll
                        for (int r = 0; r < 4; r++)
                            oacc[r] += f4c(sv[r], t4) * vv;
                    }
                }
                for (; jj < cols; jj++) {
                    float vv = buf[jj * DD + d_o];
                    #pragma unroll
                    for (int r = 0; r < 4; r++)
                        oacc[r] += S[(srb * 4 + r) * NSEQ + cb + jj] * vv;
                }
            }
            __syncthreads();
        }
        // write O for unmasked rows
        if (srb * 4 < nr) {
            #pragma unroll
            for (int r = 0; r < 4; r++) {
                int sr = srb * 4 + r;
                if (sr < nr)
                    out[((size_t)bh * NSEQ + q0 + qrow[sr]) * DD + d_o] = oacc[r] * inv_s[sr];
            }
        }
    } // m > 0

    // ===== attn write: full rows; masked rows (or m==0) are exactly uniform 1/2048 =====
    {
        float* attn = out + (size_t)BB * HH * NSEQ * DD;
        for (int i = 0; i < TQ; i++) {
            float4* rowp = (float4*)(attn + ((size_t)bh * NSEQ + q0 + i) * NSEQ);
            int sr = rowpos[i];
            if (m == 0 || sr < 0) {
                const float u = 1.0f / 2048.0f;
                float4 val = make_float4(u, u, u, u);
                for (int j4 = tid; j4 < NSEQ / 4; j4 += NTHR) rowp[j4] = val;
            } else {
                float iv = inv_s[sr];
                const float* Sp = &S[sr * NSEQ];
                for (int j4 = tid; j4 < NSEQ / 4; j4 += NTHR) {
                    int j = j4 * 4;
                    float4 o;
                    o.x = flags[j + 0] ? 0.f : Sp[pos[j + 0]] * iv;
                    o.y = flags[j + 1] ? 0.f : Sp[pos[j + 1]] * iv;
                    o.z = flags[j + 2] ? 0.f : Sp[pos[j + 2]] * iv;
                    o.w = flags[j + 3] ? 0.f : Sp[pos[j + 3]] * iv;
                    rowp[j4] = o;
                }
            }
        }
    }

    // ===== masked-row outputs (and all rows when m==0): colmean(V) =====
    for (int t = tid; t < TQ * DD; t += NTHR) {
        int i = t >> 6, dd2 = t & 63;
        if (m == 0 || rowpos[i] < 0)
            out[((size_t)bh * NSEQ + q0 + i) * DD + dd2] = g_vmean[bh * DD + dd2];
    }
}

extern "C" void kernel_launch(void* const* d_in, const int* in_sizes, int n_in,
                              void* d_out, int out_size)
{
    const float* q    = (const float*)d_in[0];
    const float* k    = (const float*)d_in[1];
    const float* v    = (const float*)d_in[2];
    const int*   mask = (const int*)d_in[3];
    float* out = (float*)d_out;

    // Opt-in to >48KB dynamic SMEM (idempotent; not a stream op, capture-safe).
    cudaFuncSetAttribute(attn_kernel, cudaFuncAttributeMaxDynamicSharedMemorySize, SMEM_BYTES);

    vmean_kernel<<<BB * HH, 256>>>(v);

    dim3 grid(NSEQ / TQ, BB * HH);
    attn_kernel<<<grid, NTHR, SMEM_BYTES>>>(q, k, v, mask, out);
}